// round 17
// baseline (speedup 1.0000x reference)
#include <cuda_runtime.h>
#include <cuda_fp16.h>
#include <math.h>

#define NMAX 50000
#define EMAX 1600000
#define FIN 16
#define TT 12
#define HID 32
#define FT (FIN*TT)   // 192 values per node
#define SB 512        // scan block size

// ---------------- scratch (static device globals; no allocation) ----------------
__device__ int    g_cnt[NMAX];                    // in-degree counts; zeroed by k_fill each run
__device__ int    g_rowptr[NMAX + 1];             // CSR row pointers
__device__ int    g_cur[NMAX];                    // fill cursors
__device__ int    g_src[EMAX];                    // CSR payload: src node only
__device__ int    g_part[256];                    // scan partials (raw per-block sums)
__device__ float  g_dis[NMAX];                    // rsqrt(degree incl. self-loop)
__device__ __half g_xh[(size_t)NMAX * FT];        // fp16 features, t-major, scaled by dis[n] after scan
__device__ __half g_aggh[(size_t)NMAX * FT];      // aggregated features fp16, t-major
__device__ float  g_A[3 * FIN * HID];             // folded W_g @ L_g_top
__device__ float  g_c[3 * HID];                   // folded biases
__device__ float  g_probs[TT];                    // softmax(att)
__device__ float  g_hsum[HID];                    // sum over nodes of relu(Hacc); zeroed by k_final

// ---------------- helpers ----------------
__device__ __forceinline__ float tanhapx(float x) {
    float y; asm("tanh.approx.f32 %0, %1;" : "=f"(y) : "f"(x)); return y;
}
__device__ __forceinline__ float sigapx(float x) {
    return fmaf(0.5f, tanhapx(0.5f * x), 0.5f);
}
union F4H2 { float4 f4; __half2 h2[4]; };

__device__ __forceinline__ unsigned h2pack(float lo, float hi) {
    __half2 h = __floats2half2_rn(lo, hi);
    return *reinterpret_cast<unsigned*>(&h);
}

// m16n8k16 row.col f16 inputs, f32 accum (C += A*B)
__device__ __forceinline__ void mma16816(float* c, const unsigned* a, const unsigned* b) {
    asm volatile(
        "mma.sync.aligned.m16n8k16.row.col.f32.f16.f16.f32 "
        "{%0,%1,%2,%3}, {%4,%5,%6,%7}, {%8,%9}, {%0,%1,%2,%3};"
        : "+f"(c[0]), "+f"(c[1]), "+f"(c[2]), "+f"(c[3])
        : "r"(a[0]), "r"(a[1]), "r"(a[2]), "r"(a[3]), "r"(b[0]), "r"(b[1]));
}

__device__ __forceinline__ void red_add(int* p) {
    asm volatile("red.global.add.s32 [%0], %1;" :: "l"(p), "r"(1) : "memory");
}

// =======================================================================
// k_pre: edge-count + fp16 transpose + (blocks 0-2) weight fold + softmax
// grid = (N+3)/4 = 12500 blocks of 256
// =======================================================================
__global__ void __launch_bounds__(256)
k_pre(const float* __restrict__ x, const int* __restrict__ ei,
      const float* __restrict__ Wz, const float* __restrict__ bz,
      const float* __restrict__ Wr, const float* __restrict__ br,
      const float* __restrict__ Wh, const float* __restrict__ bh,
      const float* __restrict__ LzW, const float* __restrict__ Lzb,
      const float* __restrict__ LrW, const float* __restrict__ Lrb,
      const float* __restrict__ LhW, const float* __restrict__ Lhb,
      const float* __restrict__ att, int N, int E) {
    __shared__ float sx[4 * FT];
    int tid = threadIdx.x;

    // --- edge-count (fire-and-forget) ---
    int gt = blockIdx.x * 256 + tid;
    if (gt < E) red_add(&g_cnt[__ldg(&ei[E + gt])]);

    // --- conversion: 4 nodes per block, [N][F][T] f32 -> [N][T][F] f16 ---
    size_t base = (size_t)blockIdx.x * 4 * FT;
    size_t lim  = (size_t)N * FT;
    #pragma unroll
    for (int i = tid; i < 4 * FT; i += 256) {
        size_t g = base + i;
        if (g < lim) sx[i] = x[g];
    }
    __syncthreads();
    {
        int nn = tid >> 6, u = tid & 63;
        int node = blockIdx.x * 4 + nn;
        if (node < N) {
            const float* s = sx + nn * FT;
            __half* d = g_xh + (size_t)node * FT;
            #pragma unroll
            for (int r = 0; r < 3; r++) {
                int o = (r << 6) + u;               // output index (t-major)
                int t = o >> 4, f = o & 15;
                d[o] = __float2half(s[f * TT + t]);
            }
        }
    }

    // --- weight fold: block g in {0,1,2} handles gate g ---
    if (blockIdx.x < 3) {
        int g = blockIdx.x;
        const float* W  = (g == 0) ? Wz : (g == 1) ? Wr : Wh;
        const float* L  = (g == 0) ? LzW : (g == 1) ? LrW : LhW;
        const float* bb = (g == 0) ? bz : (g == 1) ? br : bh;
        const float* Lb = (g == 0) ? Lzb : (g == 1) ? Lrb : Lhb;
        #pragma unroll
        for (int rep = 0; rep < 2; rep++) {
            int id = tid + rep * 256;           // 512 (f,j) pairs
            int f = id >> 5, j = id & 31;
            float s = 0.0f;
            #pragma unroll
            for (int k = 0; k < HID; k++)
                s = fmaf(__ldg(&W[f * HID + k]), __ldg(&L[k * HID + j]), s);
            g_A[(g * FIN + f) * HID + j] = s;
        }
        if (tid < HID) {
            float s = __ldg(&Lb[tid]);
            #pragma unroll
            for (int k = 0; k < HID; k++)
                s = fmaf(__ldg(&bb[k]), __ldg(&L[k * HID + tid]), s);
            g_c[g * HID + tid] = s;
        }
        if (g == 0 && tid >= 32 && tid < 64) {  // softmax on warp 1
            int l = tid & 31;
            float v = (l < TT) ? __ldg(&att[l]) : -1e30f;
            float m = v;
            #pragma unroll
            for (int o = 16; o; o >>= 1) m = fmaxf(m, __shfl_xor_sync(0xffffffffu, m, o));
            float e = (l < TT) ? __expf(v - m) : 0.0f;
            float s = e;
            #pragma unroll
            for (int o = 16; o; o >>= 1) s += __shfl_xor_sync(0xffffffffu, s, o);
            if (l < TT) g_probs[l] = e * __fdividef(1.0f, s);
        }
    }
}

// ---- scan phase A: per-block reduction of counts (raw sums into g_part) ----
__global__ void k_scan_a(int N) {
    __shared__ int ws[SB / 32];
    int tid = threadIdx.x;
    int i = blockIdx.x * SB + tid;
    int v = (i < N) ? g_cnt[i] : 0;
    #pragma unroll
    for (int o = 16; o; o >>= 1) v += __shfl_xor_sync(0xffffffffu, v, o);
    if ((tid & 31) == 0) ws[tid >> 5] = v;
    __syncthreads();
    if (tid < SB / 32) {
        int w = ws[tid];
        #pragma unroll
        for (int o = 8; o; o >>= 1) w += __shfl_xor_sync(0xffffu, w, o);
        if (tid == 0) g_part[blockIdx.x] = w;
    }
}

// ---- scan phase C: base from raw partials + block-local scan; writes
//      rowptr/cur/dis AND scales this block's xh rows by dis (coalesced).
__global__ void __launch_bounds__(SB)
k_scan_c(int N, int E, int NB) {
    __shared__ int   rs[SB / 32];
    __shared__ int   ws[SB / 32];
    __shared__ int   sbase;
    __shared__ float sdis[SB];
    int tid = threadIdx.x, lane = tid & 31, wid = tid >> 5;
    int b = blockIdx.x;

    // base = sum of g_part[0..b-1]
    int p = (tid < b) ? g_part[tid] : 0;
    #pragma unroll
    for (int o = 16; o; o >>= 1) p += __shfl_xor_sync(0xffffffffu, p, o);
    if (lane == 0) rs[wid] = p;
    __syncthreads();
    if (tid == 0) {
        int s = 0;
        #pragma unroll
        for (int k = 0; k < SB / 32; k++) s += rs[k];
        sbase = s;
    }

    // block-local inclusive scan of counts
    int i = b * SB + tid;
    int c = (i < N) ? g_cnt[i] : 0;
    int v = c;
    #pragma unroll
    for (int o = 1; o < 32; o <<= 1) {
        int t = __shfl_up_sync(0xffffffffu, v, o);
        if (lane >= o) v += t;
    }
    if (lane == 31) ws[wid] = v;
    __syncthreads();
    if (wid == 0 && lane < SB / 32) {
        int w = ws[lane];
        #pragma unroll
        for (int o = 1; o < SB / 32; o <<= 1) {
            int t = __shfl_up_sync((1u << (SB / 32)) - 1u, w, o);
            if (lane >= o) w += t;
        }
        ws[lane] = w;
    }
    __syncthreads();
    float dv = rsqrtf((float)(c + 1));           // +1 self-loop
    int excl = v - c + (wid > 0 ? ws[wid - 1] : 0) + sbase;
    if (i < N) {
        g_rowptr[i] = excl;
        g_cur[i]    = excl;
        g_dis[i]    = dv;
    }
    if (b == NB - 1 && tid == 0) g_rowptr[N] = E;

    // scale this block's xh slab: xh[n] *= dis[n]  (coalesced float4 passes)
    sdis[tid] = dv;
    __syncthreads();
    const int F4PN = FT / 8;                     // 24 float4 per node
    size_t blk4   = (size_t)b * SB * F4PN;       // first float4 of this block
    size_t lim4   = (size_t)N * F4PN;
    float4* xh4 = (float4*)g_xh;
    #pragma unroll
    for (int it = 0; it < F4PN; it++) {
        size_t idx = blk4 + (size_t)it * SB + tid;
        if (idx < lim4) {
            int nloc = (int)((idx - blk4 + 0) / F4PN);   // wrong: idx-blk4 spans strided
            // recompute properly: local float4 offset within block slab
            size_t lo = idx - blk4;
            nloc = (int)(lo / F4PN);
            __half2 dh = __float2half2_rn(sdis[nloc]);
            F4H2 vv; vv.f4 = xh4[idx];
            #pragma unroll
            for (int q = 0; q < 4; q++) vv.h2[q] = __hmul2(dh, vv.h2[q]);
            xh4[idx] = vv.f4;
        }
    }
}

// CSR fill: 4 edges per thread; payload = src only; re-zeros g_cnt.
__global__ void k_fill(const int* __restrict__ ei, int E, int N) {
    int i = blockIdx.x * blockDim.x + threadIdx.x;
    if (i < N) g_cnt[i] = 0;
    int base = i * 4;
    if (base >= E) return;
    int m = min(4, E - base);
    int s[4], d[4];
    #pragma unroll
    for (int u = 0; u < 4; u++) {
        if (u < m) {
            s[u] = __ldg(&ei[base + u]);
            d[u] = __ldg(&ei[E + base + u]);
        }
    }
    #pragma unroll
    for (int u = 0; u < 4; u++) {
        if (u < m) {
            int p = atomicAdd(&g_cur[d[u]], 1);
            g_src[p] = s[u];
        }
    }
}

// Warp-per-node gather on pre-scaled fp16 features — pure HADD2 sum,
// one final HMUL2 by dis[n].  agg[n] = dis[n]*(xh'[n] + sum_e xh'[s])
__global__ void __launch_bounds__(256)
k_gather(int N) {
    __shared__ int stage[8][32];
    int gw   = (blockIdx.x * blockDim.x + threadIdx.x) >> 5;
    int wloc = threadIdx.x >> 5;
    int lane = threadIdx.x & 31;
    if (gw >= N) return;
    int n = gw;

    int beg = g_rowptr[n];
    int end = g_rowptr[n + 1];
    float dd = g_dis[n];
    int ln = (lane < 24) ? lane : 0;        // clamped payload lane

    __half2 acc[4];
    {
        F4H2 v; v.f4 = ((const float4*)(g_xh + (size_t)n * FT))[ln];
        #pragma unroll
        for (int q = 0; q < 4; q++) acc[q] = v.h2[q];   // self term (pre-scaled)
    }

    for (int i = beg; i < end; i += 32) {
        int j = i + lane;
        if (j < end) stage[wloc][lane] = g_src[j];
        __syncwarp();
        int m = min(32, end - i);
        #pragma unroll 8
        for (int u = 0; u < m; u++) {
            int sn = stage[wloc][u];
            F4H2 v; v.f4 = ((const float4*)(g_xh + (size_t)sn * FT))[ln];
            #pragma unroll
            for (int q = 0; q < 4; q++)
                acc[q] = __hadd2(acc[q], v.h2[q]);
        }
        __syncwarp();
    }

    if (lane < 24) {
        __half2 dh = __float2half2_rn(dd);
        F4H2 st;
        #pragma unroll
        for (int q = 0; q < 4; q++) st.h2[q] = __hmul2(dh, acc[q]);
        ((float4*)(g_aggh + (size_t)n * FT))[lane] = st.f4;
    }
}

// ---- tensor-core GRU: warp handles 16 nodes via m16n8k16 HMMA ----
__device__ __forceinline__ float wzr_at(int k, int n,
                                        const float* LzW, const float* LrW) {
    int g = n >> 5, col = n & 31;
    if (k < 16) return g_A[(g * 16 + k) * 32 + col];
    const float* L = g ? LrW : LzW;
    return L[(k + 16) * 32 + col];          // bottom rows 32..63 of L
}
__device__ __forceinline__ float wh_at(int k, int n, const float* LhW) {
    if (k < 16) return g_A[(2 * 16 + k) * 32 + n];
    return LhW[(k + 16) * 32 + n];
}

__global__ void __launch_bounds__(128)
k_gru(const float* __restrict__ LzW, const float* __restrict__ LrW,
      const float* __restrict__ LhW, int N) {
    __shared__ float sp[TT];
    __shared__ float bsum[HID];

    int tid = threadIdx.x;
    if (tid < TT) sp[tid] = g_probs[tid];
    if (tid < HID) bsum[tid] = 0.0f;
    __syncthreads();

    int lane = tid & 31;
    int w = blockIdx.x * 4 + (tid >> 5);
    int NW = (N + 15) / 16;
    if (w < NW) {
        int base = w * 16;
        int qr = lane >> 2;
        int qc = lane & 3;

        // ---- weight B-fragments (once) ----
        unsigned bzr[3][8][2];
        unsigned bh[3][4][2];
        #pragma unroll
        for (int s = 0; s < 3; s++) {
            int k0 = 16 * s + 2 * qc;
            #pragma unroll
            for (int j = 0; j < 8; j++) {
                int n = 8 * j + qr;
                bzr[s][j][0] = h2pack(wzr_at(k0,     n, LzW, LrW), wzr_at(k0 + 1, n, LzW, LrW));
                bzr[s][j][1] = h2pack(wzr_at(k0 + 8, n, LzW, LrW), wzr_at(k0 + 9, n, LzW, LrW));
            }
            #pragma unroll
            for (int j = 0; j < 4; j++) {
                int n = 8 * j + qr;
                bh[s][j][0] = h2pack(wh_at(k0,     n, LhW), wh_at(k0 + 1, n, LhW));
                bh[s][j][1] = h2pack(wh_at(k0 + 8, n, LhW), wh_at(k0 + 9, n, LhW));
            }
        }
        // ---- bias fragments ----
        float bzc[8][2], bhc[4][2];
        #pragma unroll
        for (int j = 0; j < 8; j++) {
            int n = 8 * j + 2 * qc;
            bzc[j][0] = g_c[n]; bzc[j][1] = g_c[n + 1];
        }
        #pragma unroll
        for (int j = 0; j < 4; j++) {
            int n = 8 * j + 2 * qc;
            bhc[j][0] = g_c[64 + n]; bhc[j][1] = g_c[64 + n + 1];
        }

        int n0 = min(base + qr,     N - 1);
        int n1 = min(base + qr + 8, N - 1);
        const unsigned* A0 = (const unsigned*)(g_aggh + (size_t)n0 * FT) + qc;
        const unsigned* A1 = (const unsigned*)(g_aggh + (size_t)n1 * FT) + qc;

        float H[4][4], acc[4][4];
        #pragma unroll
        for (int j = 0; j < 4; j++)
            #pragma unroll
            for (int i = 0; i < 4; i++) { H[j][i] = 0.0f; acc[j][i] = 0.0f; }

        #pragma unroll 1
        for (int t = 0; t < TT; t++) {
            float p = sp[t];
            unsigned af[4];
            af[0] = A0[t * 8];     af[1] = A1[t * 8];
            af[2] = A0[t * 8 + 4]; af[3] = A1[t * 8 + 4];

            unsigned hA1[4] = { h2pack(H[0][0], H[0][1]), h2pack(H[0][2], H[0][3]),
                                h2pack(H[1][0], H[1][1]), h2pack(H[1][2], H[1][3]) };
            unsigned hA2[4] = { h2pack(H[2][0], H[2][1]), h2pack(H[2][2], H[2][3]),
                                h2pack(H[3][0], H[3][1]), h2pack(H[3][2], H[3][3]) };

            // ---- z,r GEMM ----
            float Czr[8][4];
            #pragma unroll
            for (int j = 0; j < 8; j++) {
                Czr[j][0] = bzc[j][0]; Czr[j][1] = bzc[j][1];
                Czr[j][2] = bzc[j][0]; Czr[j][3] = bzc[j][1];
            }
            #pragma unroll
            for (int j = 0; j < 8; j++) {
                mma16816(Czr[j], af,  bzr[0][j]);
                mma16816(Czr[j], hA1, bzr[1][j]);
                mma16816(Czr[j], hA2, bzr[2][j]);
            }
            float Z[4][4], R[4][4];
            #pragma unroll
            for (int j = 0; j < 4; j++)
                #pragma unroll
                for (int i = 0; i < 4; i++) {
                    Z[j][i] = sigapx(Czr[j][i]);
                    R[j][i] = sigapx(Czr[4 + j][i]) * H[j][i];
                }

            // ---- candidate GEMM ----
            unsigned rA1[4] = { h2pack(R[0][0], R[0][1]), h2pack(R[0][2], R[0][3]),
                                h2pack(R[1][0], R[1][1]), h2pack(R[1][2], R[1][3]) };
            unsigned rA2[4] = { h2pack(R[2][0], R[2][1]), h2pack(R[2][2], R[2][3]),
                                h2pack(R[3][0], R[3][1]), h2pack(R[3][2], R[3][3]) };
            float Ch[4][4];
            #pragma unroll
            for (int j = 0; j < 4; j++) {
                Ch[j][0] = bhc[j][0]; Ch[j][1] = bhc[j][1];
                Ch[j][2] = bhc[j][0]; Ch[j][3] = bhc[j][1];
            }
            #pragma unroll
            for (int j = 0; j < 4; j++) {
                mma16816(Ch[j], af,  bh[0][j]);
                mma16816(Ch[j], rA1, bh[1][j]);
                mma16816(Ch[j], rA2, bh[2][j]);
            }
            // ---- state update ----
            #pragma unroll
            for (int j = 0; j < 4; j++)
                #pragma unroll
                for (int i = 0; i < 4; i++) {
                    float ht = tanhapx(Ch[j][i]);
                    float z = Z[j][i];
                    H[j][i] = z * H[j][i] + (1.0f - z) * ht;
                    acc[j][i] = fmaf(p, H[j][i], acc[j][i]);
                }
        }

        // ---- relu + reduce ----
        bool v0 = (base + qr)     < N;
        bool v1 = (base + qr + 8) < N;
        #pragma unroll
        for (int j = 0; j < 4; j++) {
            float a0 = acc[j][0], a1 = acc[j][1], a2 = acc[j][2], a3 = acc[j][3];
            float s0 = (v0 ? fmaxf(a0, 0.0f) : 0.0f) + (v1 ? fmaxf(a2, 0.0f) : 0.0f);
            float s1 = (v0 ? fmaxf(a1, 0.0f) : 0.0f) + (v1 ? fmaxf(a3, 0.0f) : 0.0f);
            #pragma unroll
            for (int o = 4; o < 32; o <<= 1) {
                s0 += __shfl_xor_sync(0xffffffffu, s0, o);
                s1 += __shfl_xor_sync(0xffffffffu, s1, o);
            }
            if (qr == 0) {
                atomicAdd(&bsum[8 * j + 2 * qc],     s0);
                atomicAdd(&bsum[8 * j + 2 * qc + 1], s1);
            }
        }
    }
    __syncthreads();
    if (tid < HID) atomicAdd(&g_hsum[tid], bsum[tid]);
}

// Final readout; also re-zeros g_hsum for the next replay.
__global__ void k_final(const float* __restrict__ linW, const float* __restrict__ linb,
                        float* out, int N) {
    int j = threadIdx.x;   // 32 threads
    float invN = 1.0f / (float)N;
    float h = g_hsum[j];
    g_hsum[j] = 0.0f;
    float v = h * invN * linW[j];
    #pragma unroll
    for (int o = 16; o; o >>= 1) v += __shfl_xor_sync(0xffffffffu, v, o);
    if (j == 0) {
        float r = v + linb[0];
        out[0] = r > 0.0f ? r : 0.0f;
    }
}

// ---------------- launcher ----------------
extern "C" void kernel_launch(void* const* d_in, const int* in_sizes, int n_in,
                              void* d_out, int out_size) {
    const float* x    = (const float*)d_in[0];
    const int*   ei   = (const int*)  d_in[1];
    const float* att  = (const float*)d_in[2];
    const float* Wz   = (const float*)d_in[3];
    const float* bz   = (const float*)d_in[4];
    const float* Wr   = (const float*)d_in[5];
    const float* br   = (const float*)d_in[6];
    const float* Wh   = (const float*)d_in[7];
    const float* bh   = (const float*)d_in[8];
    const float* LzW  = (const float*)d_in[9];
    const float* Lzb  = (const float*)d_in[10];
    const float* LrW  = (const float*)d_in[11];
    const float* Lrb  = (const float*)d_in[12];
    const float* LhW  = (const float*)d_in[13];
    const float* Lhb  = (const float*)d_in[14];
    const float* linW = (const float*)d_in[15];
    const float* linb = (const float*)d_in[16];

    int N = in_sizes[0] / FT;
    int E = in_sizes[1] / 2;
    int NB = (N + SB - 1) / SB;
    int NW = (N + 15) / 16;             // gru warps (16 nodes each)
    int NF = (E + 3) / 4;               // fill threads (4 edges each)

    k_pre<<<(N + 3) / 4, 256>>>(x, ei, Wz, bz, Wr, br, Wh, bh,
                                LzW, Lzb, LrW, Lrb, LhW, Lhb, att, N, E);
    k_scan_a<<<NB, SB>>>(N);
    k_scan_c<<<NB, SB>>>(N, E, NB);
    k_fill<<<(NF + 255) / 256, 256>>>(ei, E, N);
    k_gather<<<(N * 32 + 255) / 256, 256>>>(N);
    k_gru<<<(NW + 3) / 4, 128>>>(LzW, LrW, LhW, N);
    k_final<<<1, 32>>>(linW, linb, (float*)d_out, N);
}